// round 1
// baseline (speedup 1.0000x reference)
#include <cuda_runtime.h>
#include <stdint.h>

// Fixed problem shape (LengthRegulator_33285996544559):
//   x:   [B=32, T=512, C=512] float32
//   dur: [B=32, T=512] int32 in [0, 12)
//   out: [B, T_out, C] float32, T_out = out_size / (B*C)
#define B_DIM 32
#define T_DIM 512
#define C_DIM 512
#define C4    (C_DIM / 4)        // 128 float4 per frame
#define MAX_TOUT (T_DIM * 11)    // dur <= 11 -> cumsum <= 5632

// Scratch: per-(b, t_out) source index. ~720 KB, static device global (no allocs).
__device__ int g_idx[B_DIM * MAX_TOUT];

// Kernel 1: per-row inclusive scan of dur, then searchsorted(cum, t, 'right')
// for every output frame t. One block per batch row, 512 threads.
__global__ void build_idx_kernel(const int* __restrict__ dur, int t_out) {
    __shared__ int s_cum[T_DIM];
    const int b   = blockIdx.x;
    const int tid = threadIdx.x;

    int d = dur[b * T_DIM + tid];
    s_cum[tid] = d > 0 ? d : 0;
    __syncthreads();

    // Hillis-Steele inclusive scan over 512 elements in shared memory.
    #pragma unroll
    for (int off = 1; off < T_DIM; off <<= 1) {
        int add = (tid >= off) ? s_cum[tid - off] : 0;
        __syncthreads();
        s_cum[tid] += add;
        __syncthreads();
    }

    // For each output frame t: first j with cum[j] > t; clamp to T-1.
    for (int t = tid; t < t_out; t += T_DIM) {
        int lo = 0, hi = T_DIM;
        while (lo < hi) {
            int mid = (lo + hi) >> 1;
            if (s_cum[mid] <= t) lo = mid + 1;
            else                 hi = mid;
        }
        if (lo > T_DIM - 1) lo = T_DIM - 1;
        g_idx[b * t_out + t] = lo;
    }
}

// Kernel 2: gather, one thread per output float4. Fully coalesced write;
// idx is warp-uniform (128 consecutive threads share one frame), x reads
// hit L2 (entire x = 32 MB << 126 MB L2).
__global__ void gather_kernel(const float4* __restrict__ x4,
                              float4* __restrict__ out4,
                              int t_out, long long n4) {
    long long g = (long long)blockIdx.x * blockDim.x + threadIdx.x;
    if (g >= n4) return;

    int c4 = (int)(g & (C4 - 1));
    int ft = (int)(g >> 7);           // frame index = b * t_out + t
    int b  = ft / t_out;

    int idx = __ldg(&g_idx[ft]);      // ft == b*t_out + t, matches g_idx layout
    const float4* src = x4 + ((long long)(b * T_DIM + idx) << 7);
    out4[g] = src[c4];
}

extern "C" void kernel_launch(void* const* d_in, const int* in_sizes, int n_in,
                              void* d_out, int out_size) {
    const float* x   = (const float*)d_in[0];
    const int*   dur = (const int*)d_in[1];
    float*       out = (float*)d_out;

    const int t_out = out_size / (B_DIM * C_DIM);

    build_idx_kernel<<<B_DIM, T_DIM>>>(dur, t_out);

    long long n4 = (long long)out_size >> 2;     // C=512 -> divisible by 4
    int threads = 256;
    long long blocks = (n4 + threads - 1) / threads;
    gather_kernel<<<(unsigned)blocks, threads>>>(
        (const float4*)x, (float4*)out, t_out, n4);
}

// round 2
// speedup vs baseline: 1.4568x; 1.4568x over previous
#include <cuda_runtime.h>
#include <stdint.h>

// Fixed problem shape (LengthRegulator_33285996544559):
//   x:   [B=32, T=512, C=512] float32
//   dur: [B=32, T=512] int32 in [0, 12)
//   out: [B, T_out, C] float32, T_out = out_size / (B*C)
#define B_DIM 32
#define T_DIM 512
#define C_DIM 512
#define C4    (C_DIM / 4)        // 128 float4 per frame
#define MAX_TOUT (T_DIM * 11)    // dur <= 11 -> cumsum <= 5632

// Scratch: per-(b, t_out) source index. ~720 KB, static device global.
__device__ int g_idx[B_DIM * MAX_TOUT];

// Kernel 1: per-row inclusive scan of dur, then searchsorted(cum, t, 'right')
// for every output frame t. One block per batch row, 512 threads.
__global__ void build_idx_kernel(const int* __restrict__ dur, int t_out) {
    __shared__ int s_cum[T_DIM];
    const int b   = blockIdx.x;
    const int tid = threadIdx.x;

    int d = dur[b * T_DIM + tid];
    s_cum[tid] = d > 0 ? d : 0;
    __syncthreads();

    #pragma unroll
    for (int off = 1; off < T_DIM; off <<= 1) {
        int add = (tid >= off) ? s_cum[tid - off] : 0;
        __syncthreads();
        s_cum[tid] += add;
        __syncthreads();
    }

    for (int t = tid; t < t_out; t += T_DIM) {
        int lo = 0, hi = T_DIM;
        while (lo < hi) {
            int mid = (lo + hi) >> 1;
            if (s_cum[mid] <= t) lo = mid + 1;
            else                 hi = mid;
        }
        if (lo > T_DIM - 1) lo = T_DIM - 1;
        g_idx[b * t_out + t] = lo;
    }
}

// Kernel 2: one WARP per output frame. Warp-uniform idx load + division;
// each thread moves 4 independent float4s (64 B) -> MLP=4 per thread,
// fully coalesced 2KB read (L2-hot) + 2KB write per warp.
__global__ void gather_kernel(const float4* __restrict__ x4,
                              float4* __restrict__ out4,
                              int t_out, int n_frames) {
    int warp = (blockIdx.x * blockDim.x + threadIdx.x) >> 5;
    int lane = threadIdx.x & 31;
    if (warp >= n_frames) return;

    int b   = warp / t_out;                    // warp-uniform
    int idx = __ldg(&g_idx[warp]);             // warp-uniform broadcast

    const float4* src = x4   + ((long long)(b * T_DIM + idx) << 7);
    float4*       dst = out4 + ((long long)warp << 7);

    float4 v0 = src[lane];
    float4 v1 = src[lane + 32];
    float4 v2 = src[lane + 64];
    float4 v3 = src[lane + 96];
    dst[lane]      = v0;
    dst[lane + 32] = v1;
    dst[lane + 64] = v2;
    dst[lane + 96] = v3;
}

extern "C" void kernel_launch(void* const* d_in, const int* in_sizes, int n_in,
                              void* d_out, int out_size) {
    const float* x   = (const float*)d_in[0];
    const int*   dur = (const int*)d_in[1];
    float*       out = (float*)d_out;

    const int t_out    = out_size / (B_DIM * C_DIM);
    const int n_frames = B_DIM * t_out;

    build_idx_kernel<<<B_DIM, T_DIM>>>(dur, t_out);

    const int threads = 256;                   // 8 warps/block -> 8 frames/block
    int blocks = (n_frames * 32 + threads - 1) / threads;
    gather_kernel<<<blocks, threads>>>(
        (const float4*)x, (float4*)out, t_out, n_frames);
}

// round 3
// speedup vs baseline: 1.6718x; 1.1476x over previous
#include <cuda_runtime.h>
#include <stdint.h>

// Fixed problem shape (LengthRegulator_33285996544559):
//   x:   [B=32, T=512, C=512] float32
//   dur: [B=32, T=512] int32 in [0, 12)
//   out: [B, T_out, C] float32, T_out = out_size / (B*C)
#define B_DIM 32
#define T_DIM 512
#define C_DIM 512
#define MAX_TOUT (T_DIM * 11)    // dur <= 11 -> cumsum <= 5632

// Scratch: per-(b, t_out) source index. ~720 KB, static device global.
__device__ int g_idx[B_DIM * MAX_TOUT];

// Kernel 1: per-row inclusive scan of dur, then SCATTER expansion:
// source token `tid` owns output frames [cum[tid]-d, cum[tid]); frames past
// the row total map to T-1. One block per batch row, 512 threads.
__global__ void build_idx_kernel(const int* __restrict__ dur, int t_out) {
    __shared__ int s_cum[T_DIM];
    const int b   = blockIdx.x;
    const int tid = threadIdx.x;

    int d = dur[b * T_DIM + tid];
    if (d < 0) d = 0;
    s_cum[tid] = d;
    __syncthreads();

    // Hillis-Steele inclusive scan over 512 elements.
    #pragma unroll
    for (int off = 1; off < T_DIM; off <<= 1) {
        int add = (tid >= off) ? s_cum[tid - off] : 0;
        __syncthreads();
        s_cum[tid] += add;
        __syncthreads();
    }

    int end   = s_cum[tid];
    int start = end - d;
    int* row  = g_idx + b * t_out;
    for (int t = start; t < end; t++) row[t] = tid;

    int total = s_cum[T_DIM - 1];
    for (int t = total + tid; t < t_out; t += T_DIM)
        row[t] = T_DIM - 1;
}

// Kernel 2: one warp per TWO output frames. All 8 LDG.128 issued before any
// store (MLP=8/thread); streaming stores (__stcs) keep x resident in L2.
__global__ void gather_kernel(const float4* __restrict__ x4,
                              float4* __restrict__ out4,
                              int t_out, int n_frames) {
    int w    = (blockIdx.x * blockDim.x + threadIdx.x) >> 5;
    int lane = threadIdx.x & 31;
    int f0   = w << 1;
    if (f0 >= n_frames) return;

    bool has2 = (f0 + 1) < n_frames;
    int  f1   = has2 ? (f0 + 1) : f0;

    int b0 = f0 / t_out;
    int b1 = f1 / t_out;
    int i0 = __ldg(&g_idx[f0]);
    int i1 = __ldg(&g_idx[f1]);

    const float4* s0 = x4 + ((long long)(b0 * T_DIM + i0) << 7);
    const float4* s1 = x4 + ((long long)(b1 * T_DIM + i1) << 7);

    float4 v0 = __ldg(&s0[lane]);
    float4 v1 = __ldg(&s0[lane + 32]);
    float4 v2 = __ldg(&s0[lane + 64]);
    float4 v3 = __ldg(&s0[lane + 96]);
    float4 u0 = __ldg(&s1[lane]);
    float4 u1 = __ldg(&s1[lane + 32]);
    float4 u2 = __ldg(&s1[lane + 64]);
    float4 u3 = __ldg(&s1[lane + 96]);

    float4* d0 = out4 + ((long long)f0 << 7);
    __stcs(&d0[lane],      v0);
    __stcs(&d0[lane + 32], v1);
    __stcs(&d0[lane + 64], v2);
    __stcs(&d0[lane + 96], v3);

    if (has2) {
        float4* d1 = out4 + ((long long)f1 << 7);
        __stcs(&d1[lane],      u0);
        __stcs(&d1[lane + 32], u1);
        __stcs(&d1[lane + 64], u2);
        __stcs(&d1[lane + 96], u3);
    }
}

extern "C" void kernel_launch(void* const* d_in, const int* in_sizes, int n_in,
                              void* d_out, int out_size) {
    const float* x   = (const float*)d_in[0];
    const int*   dur = (const int*)d_in[1];
    float*       out = (float*)d_out;

    const int t_out    = out_size / (B_DIM * C_DIM);
    const int n_frames = B_DIM * t_out;

    build_idx_kernel<<<B_DIM, T_DIM>>>(dur, t_out);

    const int threads  = 256;                  // 8 warps -> 16 frames / block
    int n_warps = (n_frames + 1) >> 1;
    int blocks  = (n_warps * 32 + threads - 1) / threads;
    gather_kernel<<<blocks, threads>>>(
        (const float4*)x, (float4*)out, t_out, n_frames);
}

// round 4
// speedup vs baseline: 1.7964x; 1.0745x over previous
#include <cuda_runtime.h>
#include <stdint.h>

// Fixed problem shape (LengthRegulator_33285996544559):
//   x:   [B=32, T=512, C=512] float32
//   dur: [B=32, T=512] int32 in [0, 12)
//   out: [B, T_out, C] float32, T_out = out_size / (B*C)
#define B_DIM 32
#define T_DIM 512
#define C_DIM 512
#define FRAMES_PER_BLOCK 16   // 8 warps x 2 frames

// Single fused kernel: each block (256 threads) serves FRAMES_PER_BLOCK
// output frames of one batch row.
//  1) load the row's 512 durations, pair-scan in smem (8 Hillis-Steele steps
//     over 256 partials)
//  2) scatter: each source token writes its id into s_idx for the frames it
//     owns that fall inside this block's window; overflow frames -> T-1
//  3) gather: warp w copies frames 2w, 2w+1 (4x LDG.128 + 4x STG.128 each,
//     loads for both frames issued before stores -> MLP=8/thread),
//     streaming stores keep x resident in L2.
__global__ void __launch_bounds__(256) lr_fused_kernel(
    const float4* __restrict__ x4,
    float4*       __restrict__ out4,
    const int*    __restrict__ dur,
    int t_out)
{
    __shared__ int s_part[256];
    __shared__ int s_idx[FRAMES_PER_BLOCK];

    const int row   = blockIdx.y;
    const int fbase = blockIdx.x * FRAMES_PER_BLOCK;   // frame offset in row
    const int tid   = threadIdx.x;

    // ---- 1) pair-scan of 512 durations with 256 threads ----
    int d0 = dur[row * T_DIM + 2 * tid];
    int d1 = dur[row * T_DIM + 2 * tid + 1];
    if (d0 < 0) d0 = 0;
    if (d1 < 0) d1 = 0;

    s_part[tid] = d0 + d1;
    __syncthreads();
    #pragma unroll
    for (int off = 1; off < 256; off <<= 1) {
        int add = (tid >= off) ? s_part[tid - off] : 0;
        __syncthreads();
        s_part[tid] += add;
        __syncthreads();
    }
    int prefix = (tid > 0) ? s_part[tid - 1] : 0;   // exclusive prefix of pair
    int total  = s_part[255];                       // row's total duration

    // token 2*tid   owns frames [prefix,      prefix+d0)
    // token 2*tid+1 owns frames [prefix+d0,   prefix+d0+d1)

    // ---- 2) scatter into this block's frame window ----
    const int fend = fbase + FRAMES_PER_BLOCK;
    {
        int s = prefix, e = prefix + d0;
        int lo = s > fbase ? s : fbase;
        int hi = e < fend ? e : fend;
        for (int t = lo; t < hi; t++) s_idx[t - fbase] = 2 * tid;

        s = e; e += d1;
        lo = s > fbase ? s : fbase;
        hi = e < fend ? e : fend;
        for (int t = lo; t < hi; t++) s_idx[t - fbase] = 2 * tid + 1;
    }
    // overflow frames (>= total) repeat the last token; disjoint from scatter
    if (tid < FRAMES_PER_BLOCK && (fbase + tid) >= total)
        s_idx[tid] = T_DIM - 1;
    __syncthreads();

    // ---- 3) gather: warp w -> frames 2w, 2w+1 ----
    const int warp = tid >> 5;
    const int lane = tid & 31;
    const int lf0  = warp << 1;
    const int f0   = fbase + lf0;
    if (f0 >= t_out) return;

    const bool has2 = (f0 + 1) < t_out;
    const int  i0 = s_idx[lf0];
    const int  i1 = s_idx[has2 ? lf0 + 1 : lf0];

    const float4* s0 = x4 + ((long long)(row * T_DIM + i0) << 7);
    const float4* s1 = x4 + ((long long)(row * T_DIM + i1) << 7);

    float4 v0 = __ldg(&s0[lane]);
    float4 v1 = __ldg(&s0[lane + 32]);
    float4 v2 = __ldg(&s0[lane + 64]);
    float4 v3 = __ldg(&s0[lane + 96]);
    float4 u0 = __ldg(&s1[lane]);
    float4 u1 = __ldg(&s1[lane + 32]);
    float4 u2 = __ldg(&s1[lane + 64]);
    float4 u3 = __ldg(&s1[lane + 96]);

    float4* dst0 = out4 + ((long long)(row * t_out + f0) << 7);
    __stcs(&dst0[lane],      v0);
    __stcs(&dst0[lane + 32], v1);
    __stcs(&dst0[lane + 64], v2);
    __stcs(&dst0[lane + 96], v3);

    if (has2) {
        float4* dst1 = dst0 + C_DIM / 4;
        __stcs(&dst1[lane],      u0);
        __stcs(&dst1[lane + 32], u1);
        __stcs(&dst1[lane + 64], u2);
        __stcs(&dst1[lane + 96], u3);
    }
}

extern "C" void kernel_launch(void* const* d_in, const int* in_sizes, int n_in,
                              void* d_out, int out_size) {
    const float* x   = (const float*)d_in[0];
    const int*   dur = (const int*)d_in[1];
    float*       out = (float*)d_out;

    const int t_out = out_size / (B_DIM * C_DIM);

    dim3 grid((t_out + FRAMES_PER_BLOCK - 1) / FRAMES_PER_BLOCK, B_DIM);
    lr_fused_kernel<<<grid, 256>>>(
        (const float4*)x, (float4*)out, dur, t_out);
}